// round 13
// baseline (speedup 1.0000x reference)
#include <cuda_runtime.h>
#include <cuda_bf16.h>
#include <cstdint>

// Only Z0[:,:,-1] = conv(X0, t=10) is nonzero.  Softmax degree-norm is a no-op.
// R13: one kernel per phase for per-launch ncu visibility.

// ---------------- device scratch ----------------
__device__ float g_obs2[2 * 8192];     // MLP input rows t=9,10
__device__ float g_s1[2 * 2048];       // accum; zeroed by combine
__device__ float g_s2[2 * 2048];       // accum; zeroed by combine
__device__ float g_s3[2 * 12288];      // accum; row0=X9, row1=X10 (pre-bias/relu)
__device__ float g_sph[12 * 256];      // accum; zeroed by combine
__device__ float g_tph[256];           // plain store (pre-bias)
__device__ float g_U[3 * 1024 * 12];   // [c][n][tau], c = feat-9
__device__ float g_Y[1024 * 12];
__device__ float g_G[3 * 1024 * 12];   // normalized (A@X) rows

// ---------------- prep: obs gather + zero out tail ----------------
__global__ void prep_kernel(const float* __restrict__ obs,
                            float* __restrict__ out) {
    int idx = blockIdx.x * blockDim.x + threadIdx.x;
    if (idx < 16384) {
        int m = idx >> 13, k = idx & 8191;
        int n = k >> 3, d = k & 7;
        g_obs2[idx] = obs[n * 96 + d * 12 + 9 + m];
    } else if (idx < 16384 + 36864) {
        out[12288 + (idx - 16384)] = 0.0f;
    }
}

// ---------------- sph split-K (coalesced) + tph ----------------
__global__ void sh_kernel(const float* __restrict__ li,
                          const float* __restrict__ gs_w1,
                          const float* __restrict__ tf,
                          const float* __restrict__ gt_w1,
                          const float* __restrict__ gt_b1) {
    int t = threadIdx.x;
    if (blockIdx.x < 96) {
        int tau = blockIdx.x >> 3, kc = blockIdx.x & 7;
        const float* lr = li + tau * 1024 + kc * 128;
        const float* w  = gs_w1 + (size_t)(kc * 128) * 256 + t;
        float acc = 0.0f;
#pragma unroll 16
        for (int k = 0; k < 128; ++k) acc += lr[k] * w[(size_t)k * 256];
        atomicAdd(&g_sph[tau * 256 + t], acc);
    } else {
        float acc = 0.0f;
#pragma unroll
        for (int k = 0; k < 36; ++k) acc += tf[k] * gt_w1[k * 256 + t];
        g_tph[t] = acc + gt_b1[t];   // pre-relu
    }
}

// ---------------- U as coalesced GEMM over all 12288 cols ------------------
// thread owns one col j; computes 12 taus (gs path) + tp (gt path);
// writes U rows for j%12 in {9,10,11}; j%12==10 also computes Y.
__global__ void __launch_bounds__(256, 4)
u_kernel(const float* __restrict__ gs_w2, const float* __restrict__ gs_b1,
         const float* __restrict__ gs_b2,
         const float* __restrict__ gt_w2, const float* __restrict__ gt_b2,
         const float* __restrict__ Bm) {
    __shared__ float sa[12 * 256];
    __shared__ float sat[256];
    __shared__ float sB[144];
    int tid = threadIdx.x;
    for (int i = tid; i < 12 * 256; i += 256)
        sa[i] = fmaxf(g_sph[i] + gs_b1[i & 255], 0.0f);
    sat[tid] = fmaxf(g_tph[tid], 0.0f);
    if (tid < 144) sB[tid] = Bm[tid];
    __syncthreads();

    int j = blockIdx.x * 256 + tid;     // 0..12287
    float acc[12];
#pragma unroll
    for (int q = 0; q < 12; ++q) acc[q] = 0.0f;
    float tp = 0.0f;
    const float* wg = gs_w2 + j;
    const float* wt = gt_w2 + j;
#pragma unroll 4
    for (int k = 0; k < 256; ++k) {
        float w = wg[(size_t)k * 12288];
        float w2 = wt[(size_t)k * 12288];
        tp += sat[k] * w2;
#pragma unroll
        for (int q = 0; q < 12; ++q) acc[q] += sa[q * 256 + k] * w;
    }
    int c = j % 12;
    if (c >= 9) {
        int n = j / 12;
        float tpv = fmaxf(tp + gt_b2[j], 0.0f);
        float bsp = gs_b2[j];
        float u[12];
#pragma unroll
        for (int q = 0; q < 12; ++q) {
            u[q] = fmaxf(acc[q] + bsp, 0.0f) + tpv;
            g_U[(c - 9) * 12288 + n * 12 + q] = u[q];
        }
        if (c == 10) {
#pragma unroll
            for (int p = 0; p < 12; ++p) {
                float y = 0.0f;
#pragma unroll
                for (int q = 0; q < 12; ++q) y += sB[p * 12 + q] * u[q];
                g_Y[n * 12 + p] = y;
            }
        }
    }
}

// ---------------- split-K GEMV (M=2), bias+relu fused on A -----------------
template<int K, int N, bool RELU>
__device__ __forceinline__ void gemv_body(const float* __restrict__ A,
                                          const float* __restrict__ bias,
                                          const float* __restrict__ W,
                                          float* __restrict__ S, int kchunk) {
    int col = (blockIdx.x * blockDim.x + threadIdx.x) * 4;
    int k0  = blockIdx.y * kchunk;
    float a00 = 0, a01 = 0, a02 = 0, a03 = 0;
    float a10 = 0, a11 = 0, a12 = 0, a13 = 0;
#pragma unroll 8
    for (int k = k0; k < k0 + kchunk; ++k) {
        const float4 w = *reinterpret_cast<const float4*>(W + (size_t)k * N + col);
        float x0 = A[k], x1 = A[K + k];
        if (RELU) {
            float bb = bias[k];
            x0 = fmaxf(x0 + bb, 0.0f); x1 = fmaxf(x1 + bb, 0.0f);
        }
        a00 += x0 * w.x; a01 += x0 * w.y; a02 += x0 * w.z; a03 += x0 * w.w;
        a10 += x1 * w.x; a11 += x1 * w.y; a12 += x1 * w.z; a13 += x1 * w.w;
    }
    atomicAdd(S + col + 0, a00); atomicAdd(S + col + 1, a01);
    atomicAdd(S + col + 2, a02); atomicAdd(S + col + 3, a03);
    atomicAdd(S + N + col + 0, a10); atomicAdd(S + N + col + 1, a11);
    atomicAdd(S + N + col + 2, a12); atomicAdd(S + N + col + 3, a13);
}

__global__ void gemv1_kernel(const float* __restrict__ W) {
    gemv_body<8192, 2048, false>(g_obs2, nullptr, W, g_s1, 64);
}
__global__ void gemv2_kernel(const float* __restrict__ W,
                             const float* __restrict__ b1) {
    gemv_body<2048, 2048, true>(g_s1, b1, W, g_s2, 16);
}
__global__ void gemv3_kernel(const float* __restrict__ W,
                             const float* __restrict__ b2) {
    gemv_body<2048, 12288, true>(g_s2, b2, W, g_s3, 64);
}

// ---------------- adjacency: warp per (ap,row), smem-staged ----------------
#define ADJ_NTHR 512
#define ADJ_NWARP (148 * (ADJ_NTHR / 32))

__device__ __forceinline__ float4 relu4b(float4 v, float4 b) {
    v.x = fmaxf(v.x + b.x, 0.0f); v.y = fmaxf(v.y + b.y, 0.0f);
    v.z = fmaxf(v.z + b.z, 0.0f); v.w = fmaxf(v.w + b.w, 0.0f);
    return v;
}

__global__ void __launch_bounds__(ADJ_NTHR, 1)
adj_kernel(const float* __restrict__ b3) {
    extern __shared__ float sm[];
    float* sY   = sm;
    float* sX10 = sm + 12288;
    float* sX9  = sm + 24576;
    int tid = threadIdx.x;
    int gw = blockIdx.x * (ADJ_NTHR / 32) + (tid >> 5);
    int lane = tid & 31;

    for (int i = tid; i < 12288 / 4; i += ADJ_NTHR) {
        ((float4*)sY)[i] = ((const float4*)g_Y)[i];
        float4 bb = ((const float4*)b3)[i % 3072];
        ((float4*)sX10)[i] = relu4b(((const float4*)(g_s3 + 12288))[i], bb);
        ((float4*)sX9)[i]  = relu4b(((const float4*)g_s3)[i], bb);
    }
    __syncthreads();

    for (int task = gw; task < 3072; task += ADJ_NWARP) {
        int ap = task >> 10;
        int i = task & 1023;
        int cidx = (ap == 0) ? 1 : (ap == 1 ? 0 : 2);   // a = 10,9,11
        const float* sX = (ap == 0) ? sX10 : sX9;
        float u[12];
#pragma unroll
        for (int q = 0; q < 12; ++q) u[q] = g_U[cidx * 12288 + i * 12 + q];
        float g[12];
#pragma unroll
        for (int q = 0; q < 12; ++q) g[q] = 0.0f;
        float rs = 0.0f;
        for (int j = lane; j < 1024; j += 32) {
            const float4* yr = (const float4*)(sY + j * 12);
            float4 ya = yr[0], yb = yr[1], yc = yr[2];
            float s = u[0]*ya.x + u[1]*ya.y + u[2] *ya.z + u[3] *ya.w
                    + u[4]*yb.x + u[5]*yb.y + u[6] *yb.z + u[7] *yb.w
                    + u[8]*yc.x + u[9]*yc.y + u[10]*yc.z + u[11]*yc.w;
            s = (s >= 0.05f) ? s : 0.0f;
            float e = __expf(s);
            rs += e;
            const float4* xr = (const float4*)(sX + j * 12);
            float4 xa = xr[0], xb = xr[1], xc = xr[2];
            g[0] += e*xa.x; g[1] += e*xa.y; g[2] += e*xa.z; g[3] += e*xa.w;
            g[4] += e*xb.x; g[5] += e*xb.y; g[6] += e*xb.z; g[7] += e*xb.w;
            g[8] += e*xc.x; g[9] += e*xc.y; g[10]+= e*xc.z; g[11]+= e*xc.w;
        }
#pragma unroll
        for (int o = 16; o; o >>= 1) {
            rs += __shfl_xor_sync(0xffffffffu, rs, o);
#pragma unroll
            for (int q = 0; q < 12; ++q)
                g[q] += __shfl_xor_sync(0xffffffffu, g[q], o);
        }
        if (lane == 0) {
            float inv = 1.0f / rs;
            float* G = g_G + task * 12;
#pragma unroll
            for (int q = 0; q < 12; ++q) G[q] = g[q] * inv;
        }
    }
}

// ---------------- combine + re-zero all accumulators ----------------
__global__ void combine_kernel(const float* __restrict__ Wf,
                               const float* __restrict__ Wb,
                               const float* __restrict__ bvec,
                               float* __restrict__ out) {
    int idx = blockIdx.x * blockDim.x + threadIdx.x;
    if (idx < 12288) {
        int n = idx / 12, f = idx % 12;
        float acc1 = bvec[f], acc2 = bvec[f];
#pragma unroll
        for (int q = 0; q < 12; ++q) {
            acc1 += g_G[n * 12 + q] * (Wf[q * 12 + f] + Wb[q * 12 + f]);
            acc2 += g_G[(1024 + n) * 12 + q] * Wf[144 + q * 12 + f]
                  + g_G[(2048 + n) * 12 + q] * Wb[144 + q * 12 + f];
        }
        out[idx] = fmaxf(acc1, 0.0f) + fmaxf(acc2, 0.0f);
    } else if (idx < 12288 + 35840) {
        int i = idx - 12288;
        if (i < 4096)        g_s1[i] = 0.0f;
        else if (i < 8192)   g_s2[i - 4096] = 0.0f;
        else if (i < 32768)  g_s3[i - 8192] = 0.0f;
        else                 g_sph[i - 32768] = 0.0f;
    }
}

#define ADJ_SMEM (3 * 12288 * sizeof(float))

// ---------------- launch ----------------
extern "C" void kernel_launch(void* const* d_in, const int* in_sizes, int n_in,
                              void* d_out, int out_size) {
    const float* obs    = (const float*)d_in[0];
    const float* tf     = (const float*)d_in[1];
    const float* fc_w1  = (const float*)d_in[2];
    const float* fc_b1  = (const float*)d_in[3];
    const float* fc_w2  = (const float*)d_in[4];
    const float* fc_b2  = (const float*)d_in[5];
    const float* fc_w3  = (const float*)d_in[6];
    const float* fc_b3  = (const float*)d_in[7];
    const float* Wf     = (const float*)d_in[8];
    const float* Wb     = (const float*)d_in[9];
    const float* bvec   = (const float*)d_in[10];
    const float* li     = (const float*)d_in[11];
    const float* gs_w1  = (const float*)d_in[12];
    const float* gs_b1  = (const float*)d_in[13];
    const float* gs_w2  = (const float*)d_in[14];
    const float* gs_b2  = (const float*)d_in[15];
    const float* gt_w1  = (const float*)d_in[16];
    const float* gt_b1  = (const float*)d_in[17];
    const float* gt_w2  = (const float*)d_in[18];
    const float* gt_b2  = (const float*)d_in[19];
    const float* Bm     = (const float*)d_in[20];
    float* out = (float*)d_out;

    cudaFuncSetAttribute(adj_kernel,
                         cudaFuncAttributeMaxDynamicSharedMemorySize, ADJ_SMEM);

    prep_kernel<<<208, 256>>>(obs, out);
    sh_kernel<<<97, 256>>>(li, gs_w1, tf, gt_w1, gt_b1);
    u_kernel<<<48, 256>>>(gs_w2, gs_b1, gs_b2, gt_w2, gt_b2, Bm);

    gemv1_kernel<<<dim3(2, 128), 256>>>(fc_w1);
    gemv2_kernel<<<dim3(2, 128), 256>>>(fc_w2, fc_b1);
    gemv3_kernel<<<dim3(12, 32), 256>>>(fc_w3, fc_b2);

    adj_kernel<<<148, ADJ_NTHR, ADJ_SMEM>>>(fc_b3);
    combine_kernel<<<94, 512>>>(Wf, Wb, bvec, out);
}

// round 14
// speedup vs baseline: 1.4434x; 1.4434x over previous
#include <cuda_runtime.h>
#include <cuda_bf16.h>
#include <cstdint>

// Only Z0[:,:,-1] = conv(X0, t=10) is nonzero.  Softmax degree-norm is a no-op.
// Single persistent kernel; weight streaming via TMA bulk copies (cp.async.bulk
// + mbarrier) into a 3-deep x 64KB smem ring; replay-safe grid barriers.

#define NBLK 148
#define NTHR 512
#define NT (NBLK * NTHR)
#define NWARP (NBLK * 16)

// ---------------- device scratch ----------------
__device__ float g_obs2[2 * 8192];     // MLP input rows t=9,10
__device__ float g_s1[2 * 2048];       // accum (no bias), zeroed in P5
__device__ float g_s2[2 * 2048];       // accum, zeroed in P5
__device__ float g_s3[2 * 12288];      // accum; row0=X9, row1=X10 (pre-bias/relu)
__device__ float g_sph[12 * 256];      // accum (no bias), zeroed in P5
__device__ float g_tph[256];           // plain store (pre-bias)
__device__ float g_U[3 * 1024 * 12];   // [c][n][tau], c = feat-9
__device__ float g_Y[1024 * 12];
__device__ float g_G[3 * 1024 * 12];   // normalized (A@X) rows

// ---------------- grid barrier (sense-reversing, replay-safe) --------------
__device__ unsigned g_bar_cnt[8];
__device__ unsigned g_bar_flag[8];

__device__ __forceinline__ void grid_barrier(int i) {
    __syncthreads();
    if (threadIdx.x == 0) {
        volatile unsigned* fl = &g_bar_flag[i];
        unsigned sense = *fl;
        __threadfence();
        unsigned old = atomicAdd(&g_bar_cnt[i], 1);
        if (old == NBLK - 1) {
            g_bar_cnt[i] = 0;
            __threadfence();
            *fl = sense ^ 1u;
        } else {
            while (*fl == sense) { }
        }
        __threadfence();
    }
    __syncthreads();
}

// ---------------- TMA bulk + mbarrier helpers ----------------
__device__ __forceinline__ uint32_t smem_u32(const void* p) {
    return (uint32_t)__cvta_generic_to_shared(p);
}
__device__ __forceinline__ void mbar_init(uint32_t mbar, uint32_t cnt) {
    asm volatile("mbarrier.init.shared.b64 [%0], %1;" :: "r"(mbar), "r"(cnt)
                 : "memory");
}
__device__ __forceinline__ void mbar_expect_tx(uint32_t mbar, uint32_t bytes) {
    asm volatile("mbarrier.arrive.expect_tx.shared.b64 _, [%0], %1;"
                 :: "r"(mbar), "r"(bytes) : "memory");
}
__device__ __forceinline__ void bulk_g2s(uint32_t dst, const void* src,
                                         uint32_t bytes, uint32_t mbar) {
    asm volatile(
        "cp.async.bulk.shared::cluster.global.mbarrier::complete_tx::bytes "
        "[%0], [%1], %2, [%3];"
        :: "r"(dst), "l"(src), "r"(bytes), "r"(mbar) : "memory");
}
__device__ __forceinline__ void mbar_wait(uint32_t mbar, uint32_t parity) {
    uint32_t done = 0;
    while (!done) {
        asm volatile(
            "{\n\t.reg .pred p;\n\t"
            "mbarrier.try_wait.parity.shared.b64 p, [%1], %2, 0x989680;\n\t"
            "selp.b32 %0, 1, 0, p;\n\t}"
            : "=r"(done) : "r"(mbar), "r"(parity) : "memory");
    }
}

// ---- TMA-streamed gemv: block owns 2048-col strip x [k0,k1) rows ----------
// smem ring: 3 slots x 8 rows x 2048 floats (192KB). A staged w/ bias+relu.
#define ROWS_PER_STAGE 8
#define SLOT_FLOATS (ROWS_PER_STAGE * 2048)
#define GB_SA0 49152
#define GB_SA1 49280
#define GB_MBAR 49408          // byte off 197632, 8B-aligned

template<int NFULL, bool RELU>
__device__ __forceinline__ void gemv_tma(const float* __restrict__ A,
                                         const float* __restrict__ bias,
                                         const float* __restrict__ W,
                                         float* __restrict__ S,
                                         int c0, int k0, int k1, int K,
                                         float* sm) {
    const int tid = threadIdx.x;
    float* bufs = sm;
    float* sA0 = sm + GB_SA0;
    float* sA1 = sm + GB_SA1;
    const uint32_t mb0 = smem_u32(sm + GB_MBAR);
    const uint32_t bufb = smem_u32(bufs);

    const int cnt = k1 - k0;                 // <= 86
    const int nst = (cnt + ROWS_PER_STAGE - 1) / ROWS_PER_STAGE;

    if (tid < cnt) {
        float x0 = A[k0 + tid], x1 = A[K + k0 + tid];
        if (RELU) {
            float bb = bias[k0 + tid];
            x0 = fmaxf(x0 + bb, 0.0f); x1 = fmaxf(x1 + bb, 0.0f);
        }
        sA0[tid] = x0; sA1[tid] = x1;
    }
    if (tid == 0) {
        mbar_init(mb0 + 0, 1);
        mbar_init(mb0 + 8, 1);
        mbar_init(mb0 + 16, 1);
    }
    __syncthreads();

    // producer issue for stage s
    auto issue = [&](int s) {
        int r0 = s * ROWS_PER_STAGE;
        int rn = cnt - r0; if (rn > ROWS_PER_STAGE) rn = ROWS_PER_STAGE;
        uint32_t mb = mb0 + (s % 3) * 8;
        uint32_t dst = bufb + ((s % 3) * SLOT_FLOATS << 2);
        mbar_expect_tx(mb, (uint32_t)(rn * 8192));
        if (NFULL == 2048) {
            bulk_g2s(dst, W + (size_t)(k0 + r0) * NFULL,
                     (uint32_t)(rn * 8192), mb);
        } else {
            for (int r = 0; r < rn; ++r)
                bulk_g2s(dst + (uint32_t)(r * 2048 * 4),
                         W + (size_t)(k0 + r0 + r) * NFULL + c0, 8192, mb);
        }
    };

    if (tid == 0) {
        issue(0);
        if (nst > 1) issue(1);
        if (nst > 2) issue(2);
    }

    float a00 = 0, a01 = 0, a02 = 0, a03 = 0;
    float a10 = 0, a11 = 0, a12 = 0, a13 = 0;
    for (int s = 0; s < nst; ++s) {
        mbar_wait(mb0 + (s % 3) * 8, (uint32_t)((s / 3) & 1));
        int r0 = s * ROWS_PER_STAGE;
        int rn = cnt - r0; if (rn > ROWS_PER_STAGE) rn = ROWS_PER_STAGE;
        const float* bf = bufs + (s % 3) * SLOT_FLOATS + tid * 4;
#pragma unroll 8
        for (int r = 0; r < rn; ++r) {
            float4 w = *reinterpret_cast<const float4*>(bf + r * 2048);
            float x0 = sA0[r0 + r], x1 = sA1[r0 + r];
            a00 += x0 * w.x; a01 += x0 * w.y; a02 += x0 * w.z; a03 += x0 * w.w;
            a10 += x1 * w.x; a11 += x1 * w.y; a12 += x1 * w.z; a13 += x1 * w.w;
        }
        __syncthreads();                    // slot (s%3) free
        if (tid == 0 && s + 3 < nst) issue(s + 3);
    }

    int col = c0 + tid * 4;
    atomicAdd(S + col + 0, a00); atomicAdd(S + col + 1, a01);
    atomicAdd(S + col + 2, a02); atomicAdd(S + col + 3, a03);
    atomicAdd(S + NFULL + col + 0, a10); atomicAdd(S + NFULL + col + 1, a11);
    atomicAdd(S + NFULL + col + 2, a12); atomicAdd(S + NFULL + col + 3, a13);
    __syncthreads();                        // protect smem before reuse
}

#define SMEM_FLOATS 49416                   // 197664 B

__device__ __forceinline__ float4 relu4b(float4 v, float4 b) {
    v.x = fmaxf(v.x + b.x, 0.0f); v.y = fmaxf(v.y + b.y, 0.0f);
    v.z = fmaxf(v.z + b.z, 0.0f); v.w = fmaxf(v.w + b.w, 0.0f);
    return v;
}

// ---------------- the single mega kernel ----------------
__global__ void __launch_bounds__(NTHR, 1)
mega9_kernel(const float* __restrict__ obs,
             const float* __restrict__ tf,
             const float* __restrict__ fc_w1, const float* __restrict__ b1,
             const float* __restrict__ fc_w2, const float* __restrict__ b2,
             const float* __restrict__ fc_w3, const float* __restrict__ b3,
             const float* __restrict__ Wf, const float* __restrict__ Wb,
             const float* __restrict__ bvec,
             const float* __restrict__ li,
             const float* __restrict__ gs_w1, const float* __restrict__ gs_b1,
             const float* __restrict__ gs_w2, const float* __restrict__ gs_b2,
             const float* __restrict__ gt_w1, const float* __restrict__ gt_b1,
             const float* __restrict__ gt_w2, const float* __restrict__ gt_b2,
             const float* __restrict__ Bm,
             float* __restrict__ out) {
    extern __shared__ float sm[];

    const int tid = threadIdx.x, bid = blockIdx.x;
    const int gt = bid * NTHR + tid;
    const int lane = tid & 31;
    const int gw = gt >> 5;

    // ======== P0: obs gather, out-tail zero, sph split-K (coalesced), tph ==
    for (int i = gt; i < 16384 + 36864; i += NT) {
        if (i < 16384) {
            int m = i >> 13, k = i & 8191;
            int n = k >> 3, d = k & 7;
            g_obs2[i] = obs[n * 96 + d * 12 + 9 + m];
        } else {
            out[12288 + (i - 16384)] = 0.0f;
        }
    }
    if (gt < 24576) {                       // sph: 12 tau x 8 kc x 256 t
        int t = gt & 255;
        int rr = gt >> 8;
        int tau = rr / 8, kc = rr & 7;
        const float* lr = li + tau * 1024 + kc * 128;
        const float* w  = gs_w1 + (size_t)(kc * 128) * 256 + t;
        float acc = 0.0f;
#pragma unroll 16
        for (int k = 0; k < 128; ++k) acc += lr[k] * w[(size_t)k * 256];
        atomicAdd(&g_sph[tau * 256 + t], acc);
    } else if (gt < 24832) {                // tph
        int t = gt - 24576;
        float acc = 0.0f;
#pragma unroll
        for (int k = 0; k < 36; ++k) acc += tf[k] * gt_w1[k * 256 + t];
        g_tph[t] = acc;                     // bias at read
    }
    grid_barrier(0);

    // ======== P1: u (blocks 0..47)  ||  gemv1 TMA (48..147) ================
    if (bid < 48) {
        int lw = bid * 16 + (tid >> 5);     // 0..767
        for (int task = lw; task < 3072; task += 768) {
            int n = task / 3, c = task - n * 3;
            int j = n * 12 + 9 + c;
            float wg[8], wt[8], bg[8];
#pragma unroll
            for (int i = 0; i < 8; ++i) {
                int k = lane + 32 * i;
                wg[i] = gs_w2[(size_t)k * 12288 + j];
                wt[i] = gt_w2[(size_t)k * 12288 + j];
                bg[i] = gs_b1[k];
            }
            float tp = 0.0f;
#pragma unroll
            for (int i = 0; i < 8; ++i) {
                int k = lane + 32 * i;
                tp += fmaxf(g_tph[k] + gt_b1[k], 0.0f) * wt[i];
            }
#pragma unroll
            for (int o = 16; o; o >>= 1) tp += __shfl_xor_sync(0xffffffffu, tp, o);
            float tpv = fmaxf(tp + gt_b2[j], 0.0f);
            float bsp = gs_b2[j];
#pragma unroll
            for (int tau = 0; tau < 12; ++tau) {
                float sp = 0.0f;
#pragma unroll
                for (int i = 0; i < 8; ++i)
                    sp += fmaxf(g_sph[tau * 256 + lane + 32 * i] + bg[i], 0.0f) * wg[i];
#pragma unroll
                for (int o = 16; o; o >>= 1) sp += __shfl_xor_sync(0xffffffffu, sp, o);
                if (lane == tau)
                    g_U[c * 12288 + n * 12 + tau] = fmaxf(sp + bsp, 0.0f) + tpv;
            }
        }
    } else {
        int cb = bid - 48;                  // 0..99
        int k0 = (cb * 8192) / 100;
        int k1 = ((cb + 1) * 8192) / 100;
        gemv_tma<2048, false>(g_obs2, nullptr, fc_w1, g_s1, 0, k0, k1, 8192, sm);
    }
    grid_barrier(1);

    // ======== P2: gemv2 TMA, all 148 blocks ================================
    {
        int k0 = (bid * 2048) / 148;
        int k1 = ((bid + 1) * 2048) / 148;
        gemv_tma<2048, true>(g_s1, b1, fc_w2, g_s2, 0, k0, k1, 2048, sm);
    }
    grid_barrier(2);

    // ======== P3: gemv3 TMA (blocks 0..143) + Y (144..147) =================
    if (bid < 144) {
        int s  = bid % 6;                   // col strip
        int ci = bid / 6;                   // 0..23
        int k0 = (ci * 2048) / 24;
        int k1 = ((ci + 1) * 2048) / 24;
        gemv_tma<12288, true>(g_s2, b2, fc_w3, g_s3, s * 2048, k0, k1, 2048, sm);
    } else {
        int n = (bid - 144) * NTHR + tid;
        if (n < 1024) {
            float u[12];
#pragma unroll
            for (int q = 0; q < 12; ++q) u[q] = g_U[12288 + n * 12 + q];
#pragma unroll
            for (int p = 0; p < 12; ++p) {
                float acc = 0.0f;
#pragma unroll
                for (int q = 0; q < 12; ++q) acc += Bm[p * 12 + q] * u[q];
                g_Y[n * 12 + p] = acc;
            }
        }
    }
    grid_barrier(3);

    // ======== P4: stage Y/X in smem, fused exp-adjacency + SpMM ============
    {
        float* sY   = sm;
        float* sX10 = sm + 12288;
        float* sX9  = sm + 24576;
        for (int i = tid; i < 12288 / 4; i += NTHR) {
            ((float4*)sY)[i] = ((const float4*)g_Y)[i];
            float4 bb = ((const float4*)b3)[i % 3072];
            ((float4*)sX10)[i] = relu4b(((const float4*)(g_s3 + 12288))[i], bb);
            ((float4*)sX9)[i]  = relu4b(((const float4*)g_s3)[i], bb);
        }
        __syncthreads();
        for (int task = gw; task < 3072; task += NWARP) {
            int ap = task >> 10;
            int i = task & 1023;
            int cidx = (ap == 0) ? 1 : (ap == 1 ? 0 : 2);   // a = 10,9,11
            const float* sX = (ap == 0) ? sX10 : sX9;
            float u[12];
#pragma unroll
            for (int q = 0; q < 12; ++q) u[q] = g_U[cidx * 12288 + i * 12 + q];
            float g[12];
#pragma unroll
            for (int q = 0; q < 12; ++q) g[q] = 0.0f;
            float rs = 0.0f;
            for (int j = lane; j < 1024; j += 32) {
                const float4* yr = (const float4*)(sY + j * 12);
                float4 ya = yr[0], yb = yr[1], yc = yr[2];
                float s = u[0]*ya.x + u[1]*ya.y + u[2] *ya.z + u[3] *ya.w
                        + u[4]*yb.x + u[5]*yb.y + u[6] *yb.z + u[7] *yb.w
                        + u[8]*yc.x + u[9]*yc.y + u[10]*yc.z + u[11]*yc.w;
                s = (s >= 0.05f) ? s : 0.0f;
                float e = __expf(s);
                rs += e;
                const float4* xr = (const float4*)(sX + j * 12);
                float4 xa = xr[0], xb = xr[1], xc = xr[2];
                g[0] += e*xa.x; g[1] += e*xa.y; g[2] += e*xa.z; g[3] += e*xa.w;
                g[4] += e*xb.x; g[5] += e*xb.y; g[6] += e*xb.z; g[7] += e*xb.w;
                g[8] += e*xc.x; g[9] += e*xc.y; g[10]+= e*xc.z; g[11]+= e*xc.w;
            }
#pragma unroll
            for (int o = 16; o; o >>= 1) {
                rs += __shfl_xor_sync(0xffffffffu, rs, o);
#pragma unroll
                for (int q = 0; q < 12; ++q)
                    g[q] += __shfl_xor_sync(0xffffffffu, g[q], o);
            }
            if (lane == 0) {
                float inv = 1.0f / rs;
                float* G = g_G + task * 12;
#pragma unroll
                for (int q = 0; q < 12; ++q) G[q] = g[q] * inv;
            }
        }
    }
    grid_barrier(4);

    // ======== P5: combine + zero accumulators ==============================
    if (gt < 12288 + 35840) {
        int idx = gt;
        if (idx < 12288) {
            int n = idx / 12, f = idx % 12;
            float acc1 = bvec[f], acc2 = bvec[f];
#pragma unroll
            for (int q = 0; q < 12; ++q) {
                acc1 += g_G[n * 12 + q] * (Wf[q * 12 + f] + Wb[q * 12 + f]);
                acc2 += g_G[(1024 + n) * 12 + q] * Wf[144 + q * 12 + f]
                      + g_G[(2048 + n) * 12 + q] * Wb[144 + q * 12 + f];
            }
            out[idx] = fmaxf(acc1, 0.0f) + fmaxf(acc2, 0.0f);
        } else {
            int i = idx - 12288;
            if (i < 4096)        g_s1[i] = 0.0f;
            else if (i < 8192)   g_s2[i - 4096] = 0.0f;
            else if (i < 32768)  g_s3[i - 8192] = 0.0f;
            else                 g_sph[i - 32768] = 0.0f;
        }
    }
}

// ---------------- launch ----------------
extern "C" void kernel_launch(void* const* d_in, const int* in_sizes, int n_in,
                              void* d_out, int out_size) {
    const float* obs    = (const float*)d_in[0];
    const float* tf     = (const float*)d_in[1];
    const float* fc_w1  = (const float*)d_in[2];
    const float* fc_b1  = (const float*)d_in[3];
    const float* fc_w2  = (const float*)d_in[4];
    const float* fc_b2  = (const float*)d_in[5];
    const float* fc_w3  = (const float*)d_in[6];
    const float* fc_b3  = (const float*)d_in[7];
    const float* Wf     = (const float*)d_in[8];
    const float* Wb     = (const float*)d_in[9];
    const float* bvec   = (const float*)d_in[10];
    const float* li     = (const float*)d_in[11];
    const float* gs_w1  = (const float*)d_in[12];
    const float* gs_b1  = (const float*)d_in[13];
    const float* gs_w2  = (const float*)d_in[14];
    const float* gs_b2  = (const float*)d_in[15];
    const float* gt_w1  = (const float*)d_in[16];
    const float* gt_b1  = (const float*)d_in[17];
    const float* gt_w2  = (const float*)d_in[18];
    const float* gt_b2  = (const float*)d_in[19];
    const float* Bm     = (const float*)d_in[20];
    float* out = (float*)d_out;

    cudaFuncSetAttribute(mega9_kernel,
                         cudaFuncAttributeMaxDynamicSharedMemorySize,
                         SMEM_FLOATS * sizeof(float));

    mega9_kernel<<<NBLK, NTHR, SMEM_FLOATS * sizeof(float)>>>(
        obs, tf, fc_w1, fc_b1, fc_w2, fc_b2, fc_w3, fc_b3,
        Wf, Wb, bvec, li, gs_w1, gs_b1, gs_w2, gs_b2,
        gt_w1, gt_b1, gt_w2, gt_b2, Bm, out);
}